// round 2
// baseline (speedup 1.0000x reference)
#include <cuda_runtime.h>

// Problem constants (from reference)
#define KORD 8
#define NUMI 15
#define GBAS (NUMI + KORD)        // 23 basis functions
#define NGRID (NUMI + 2*KORD + 1) // 32 grid points
#define BB 1024
#define NN 34
#define HH 256
#define WW 256

#define IMG_FLOATS (2 * HH * WW)       // 131072 floats per batch image
#define IMG_F4     (IMG_FLOATS / 4)    // 32768 float4 per batch image

// L2-persistence split: first NP images get evict-normal (write-back, stays
// resident in L2 across graph replays); the rest are streamed with evict-first
// so they never displace the persistent region. 192 images = 96 MB < 126 MB L2.
#define NP_IMAGES 192

// grid[i] = -2 + (i-8)*h, h = 4/15  — folded to constants at compile time
__device__ __forceinline__ float grid_pt(int i) {
    const float h = 4.0f / 15.0f;
    return -2.0f + (float)(i - KORD) * h;
}

// Order-8 B-spline KAN edge: base[id]*silu(x) + sum_j coef[id][j] * B_j(x)
// Knot spacings are compile-time constants -> reciprocal multiplies, pure FFMA.
__device__ __forceinline__ float spline_apply_one(float x, int id,
                                                  const float* __restrict__ coef,
                                                  const float* __restrict__ base) {
    float b[NGRID - 1];
#pragma unroll
    for (int j = 0; j < NGRID - 1; j++) {
        b[j] = (x >= grid_pt(j) && x < grid_pt(j + 1)) ? 1.0f : 0.0f;
    }
#pragma unroll
    for (int d = 1; d <= KORD; d++) {
#pragma unroll
        for (int j = 0; j <= (NGRID - 2) - d; j++) {
            float rl = 1.0f / (grid_pt(j + d) - grid_pt(j));         // const
            float rr = 1.0f / (grid_pt(j + d + 1) - grid_pt(j + 1)); // const
            float left  = (x - grid_pt(j)) * rl;
            float right = (grid_pt(j + d + 1) - x) * rr;
            b[j] = left * b[j] + right * b[j + 1];
        }
    }
    float s = 0.0f;
    const float* crow = coef + id * GBAS;
#pragma unroll
    for (int j = 0; j < GBAS; j++) s += crow[j] * b[j];
    float silu = x / (1.0f + expf(-x));
    return base[id] * silu + s;
}

// One block per batch image. Phase 1: zero the block-owned 512 KB image
// (evict-normal for the L2-persistent prefix, evict-first streaming for the
// rest). Phase 2: after a block-local sync, 34 threads evaluate the two
// stacked KAN splines and scatter into the block-owned region.
__global__ void __launch_bounds__(256)
fused_kernel(const float* __restrict__ xv,
             const float* __restrict__ dcoef,
             const float* __restrict__ dbase,
             const float* __restrict__ ccoef,
             const float* __restrict__ cbase,
             float* __restrict__ out) {
    const int b = blockIdx.x;
    float* img = out + (size_t)b * IMG_FLOATS;
    float4* img4 = (float4*)img;
    const float4 z = make_float4(0.f, 0.f, 0.f, 0.f);

    if (b < NP_IMAGES) {
        // persistent region: default (evict-normal) write-back stores
#pragma unroll 4
        for (int i = threadIdx.x; i < IMG_F4; i += 256) img4[i] = z;
    } else {
        // streaming region: evict-first, protects the persistent lines
#pragma unroll 4
        for (int i = threadIdx.x; i < IMG_F4; i += 256) __stcs(&img4[i], z);
    }
    __syncthreads();

    const int n = threadIdx.x;
    if (n >= NN) return;

    const float* vb = xv + (size_t)b * NN * 5;
    const float* v = vb + n * 5;
    float power = v[0];
    int cx = (int)rintf(v[1]);
    int cy = (int)rintf(v[2]);
    int dev = (int)v[3];
    int cat = (int)v[4];

    // Last-write-wins in index order: if any LATER point in this batch hits
    // the same (cy,cx), this point's writes are dead — skip them.
    for (int m = n + 1; m < NN; m++) {
        int mx = (int)rintf(vb[m * 5 + 1]);
        int my = (int)rintf(vb[m * 5 + 2]);
        if (mx == cx && my == cy) return;
    }

    float p = spline_apply_one(power, dev, dcoef, dbase);
    p       = spline_apply_one(p,     cat, ccoef, cbase);

    int pix = cy * WW + cx;
    img[pix] = p;                 // channel 0
    img[HH * WW + pix] = power;   // channel 1
}

extern "C" void kernel_launch(void* const* d_in, const int* in_sizes, int n_in,
                              void* d_out, int out_size) {
    const float* xv    = (const float*)d_in[0]; // (1024,34,5)
    const float* dcoef = (const float*)d_in[1]; // (34,23)
    const float* dbase = (const float*)d_in[2]; // (34,)
    const float* ccoef = (const float*)d_in[3]; // (5,23)
    const float* cbase = (const float*)d_in[4]; // (5,)
    float* out = (float*)d_out;                 // (1024,2,256,256)

    fused_kernel<<<BB, 256>>>(xv, dcoef, dbase, ccoef, cbase, out);
}

// round 3
// speedup vs baseline: 1.0260x; 1.0260x over previous
#include <cuda_runtime.h>

// Problem constants (from reference)
#define KORD 8
#define NUMI 15
#define GBAS (NUMI + KORD)        // 23 basis functions
#define BB 1024
#define NN 34
#define HH 256
#define WW 256

#define IMG_FLOATS (2 * HH * WW)       // 131072 floats per batch image
#define IMG_F4     (IMG_FLOATS / 4)    // 32768 float4 per batch image

// L2-persistence split: first NP images get evict-normal (write-back, may stay
// resident in L2 across graph replays); the rest are streamed with evict-first
// so they never displace the resident region. 192 images = 96 MB < 126 MB L2.
#define NP_IMAGES 192

// Order-8 B-spline KAN edge via local de Boor: only the K+1=9 basis functions
// covering x are nonzero. Uniform knots (h = 4/15) make every denominator in
// the triangular recurrence equal to the constant j -> pure FFMA, 9 registers.
// Out-of-range x (m<0 or m>30): all indicators in the reference are zero, so
// the spline sum vanishes and only base*silu survives.
__device__ __forceinline__ float spline_apply_one(float x, int id,
                                                  const float* __restrict__ coef,
                                                  const float* __restrict__ base) {
    float res = base[id] * (x / (1.0f + expf(-x)));   // base * silu(x)

    const float h    = 4.0f / 15.0f;
    const float invh = 15.0f / 4.0f;
    const float g0   = -2.0f - (float)KORD * h;       // grid[0]

    float u = (x - g0) * invh;                        // position in knot units
    float mf = floorf(u);
    int m = (int)mf;
    if (m < 0 || m > 30) return res;                  // outside knot range
    float t = u - mf;                                 // local coord in [0,1)

    // de Boor: N[r] = B_{m-8+r}(x) after the last iteration
    float N[KORD + 1];
    N[0] = 1.0f;
#pragma unroll
    for (int j = 1; j <= KORD; j++) {
        const float invj = 1.0f / (float)j;           // compile-time constant
        float saved = 0.0f;
#pragma unroll
        for (int r = 0; r < j; r++) {
            float temp = N[r] * invj;
            N[r] = saved + ((float)(r + 1) - t) * temp;
            saved = (t + (float)(j - 1 - r)) * temp;
        }
        N[j] = saved;
    }

    const float* crow = coef + id * GBAS;
#pragma unroll
    for (int r = 0; r <= KORD; r++) {
        int jdx = m - KORD + r;
        if (jdx >= 0 && jdx < GBAS)
            res += crow[jdx] * N[r];
    }
    return res;
}

// One block per batch image. Phase 1: zero the block-owned 512 KB image.
// Phase 2: block-local sync, then 34 threads evaluate the stacked KAN splines
// and scatter into the block-owned region (no cross-block ordering needed).
__global__ void __launch_bounds__(256, 6)
fused_kernel(const float* __restrict__ xv,
             const float* __restrict__ dcoef,
             const float* __restrict__ dbase,
             const float* __restrict__ ccoef,
             const float* __restrict__ cbase,
             float* __restrict__ out) {
    const int b = blockIdx.x;
    float* img = out + (size_t)b * IMG_FLOATS;
    float4* img4 = (float4*)img;
    const float4 z = make_float4(0.f, 0.f, 0.f, 0.f);

    if (b < NP_IMAGES) {
        // persistent region: default (evict-normal) write-back stores
#pragma unroll 4
        for (int i = threadIdx.x; i < IMG_F4; i += 256) img4[i] = z;
    } else {
        // streaming region: evict-first, protects the persistent lines
#pragma unroll 4
        for (int i = threadIdx.x; i < IMG_F4; i += 256) __stcs(&img4[i], z);
    }
    __syncthreads();

    const int n = threadIdx.x;
    if (n >= NN) return;

    const float* vb = xv + (size_t)b * NN * 5;
    const float* v = vb + n * 5;
    float power = v[0];
    int cx = (int)rintf(v[1]);
    int cy = (int)rintf(v[2]);
    int dev = (int)v[3];
    int cat = (int)v[4];

    // Last-write-wins in index order: if any LATER point in this batch hits
    // the same (cy,cx), this point's writes are dead — skip them.
    for (int m = n + 1; m < NN; m++) {
        int mx = (int)rintf(vb[m * 5 + 1]);
        int my = (int)rintf(vb[m * 5 + 2]);
        if (mx == cx && my == cy) return;
    }

    float p = spline_apply_one(power, dev, dcoef, dbase);
    p       = spline_apply_one(p,     cat, ccoef, cbase);

    int pix = cy * WW + cx;
    img[pix] = p;                 // channel 0
    img[HH * WW + pix] = power;   // channel 1
}

extern "C" void kernel_launch(void* const* d_in, const int* in_sizes, int n_in,
                              void* d_out, int out_size) {
    const float* xv    = (const float*)d_in[0]; // (1024,34,5)
    const float* dcoef = (const float*)d_in[1]; // (34,23)
    const float* dbase = (const float*)d_in[2]; // (34,)
    const float* ccoef = (const float*)d_in[3]; // (5,23)
    const float* cbase = (const float*)d_in[4]; // (5,)
    float* out = (float*)d_out;                 // (1024,2,256,256)

    fused_kernel<<<BB, 256>>>(xv, dcoef, dbase, ccoef, cbase, out);
}

// round 4
// speedup vs baseline: 1.0307x; 1.0046x over previous
#include <cuda_runtime.h>

// Problem constants (from reference)
#define KORD 8
#define NUMI 15
#define GBAS (NUMI + KORD)        // 23 basis functions
#define BB 1024
#define NN 34
#define HH 256
#define WW 256

#define IMG_FLOATS (2 * HH * WW)       // 131072 floats per batch image
#define IMG_F4     (IMG_FLOATS / 4)    // 32768 float4 per batch image

// Order-8 B-spline KAN edge via local de Boor: only the K+1=9 basis functions
// covering x are nonzero. Uniform knots (h = 4/15) make every denominator in
// the triangular recurrence equal to the constant j -> pure FFMA, 9 registers.
// Out-of-range x (m<0 or m>30): all indicators in the reference are zero, so
// the spline sum vanishes and only base*silu survives.
__device__ __forceinline__ float spline_apply_one(float x, int id,
                                                  const float* __restrict__ coef,
                                                  const float* __restrict__ base) {
    float res = base[id] * (x / (1.0f + expf(-x)));   // base * silu(x)

    const float h    = 4.0f / 15.0f;
    const float invh = 15.0f / 4.0f;
    const float g0   = -2.0f - (float)KORD * h;       // grid[0]

    float u = (x - g0) * invh;                        // position in knot units
    float mf = floorf(u);
    int m = (int)mf;
    if (m < 0 || m > 30) return res;                  // outside knot range
    float t = u - mf;                                 // local coord in [0,1)

    // de Boor: N[r] = B_{m-8+r}(x) after the last iteration
    float N[KORD + 1];
    N[0] = 1.0f;
#pragma unroll
    for (int j = 1; j <= KORD; j++) {
        const float invj = 1.0f / (float)j;           // compile-time constant
        float saved = 0.0f;
#pragma unroll
        for (int r = 0; r < j; r++) {
            float temp = N[r] * invj;
            N[r] = saved + ((float)(r + 1) - t) * temp;
            saved = (t + (float)(j - 1 - r)) * temp;
        }
        N[j] = saved;
    }

    const float* crow = coef + id * GBAS;
#pragma unroll
    for (int r = 0; r <= KORD; r++) {
        int jdx = m - KORD + r;
        if (jdx >= 0 && jdx < GBAS)
            res += crow[jdx] * N[r];
    }
    return res;
}

// One block per batch image. Phase 1: zero the block-owned 512 KB image with
// plain write-back float4 stores (the store path that measured 6.4 TB/s).
// Phase 2: block-local sync, then 34 threads evaluate the stacked KAN splines
// and scatter into the block-owned region (no cross-block ordering needed).
__global__ void __launch_bounds__(256, 6)
fused_kernel(const float* __restrict__ xv,
             const float* __restrict__ dcoef,
             const float* __restrict__ dbase,
             const float* __restrict__ ccoef,
             const float* __restrict__ cbase,
             float* __restrict__ out) {
    const int b = blockIdx.x;
    float* img = out + (size_t)b * IMG_FLOATS;
    float4* img4 = (float4*)img;
    const float4 z = make_float4(0.f, 0.f, 0.f, 0.f);

#pragma unroll 8
    for (int i = threadIdx.x; i < IMG_F4; i += 256) img4[i] = z;

    __syncthreads();

    const int n = threadIdx.x;
    if (n >= NN) return;

    const float* vb = xv + (size_t)b * NN * 5;
    const float* v = vb + n * 5;
    float power = v[0];
    int cx = (int)rintf(v[1]);
    int cy = (int)rintf(v[2]);
    int dev = (int)v[3];
    int cat = (int)v[4];

    // Last-write-wins in index order: if any LATER point in this batch hits
    // the same (cy,cx), this point's writes are dead — skip them.
    for (int m = n + 1; m < NN; m++) {
        int mx = (int)rintf(vb[m * 5 + 1]);
        int my = (int)rintf(vb[m * 5 + 2]);
        if (mx == cx && my == cy) return;
    }

    float p = spline_apply_one(power, dev, dcoef, dbase);
    p       = spline_apply_one(p,     cat, ccoef, cbase);

    int pix = cy * WW + cx;
    img[pix] = p;                 // channel 0
    img[HH * WW + pix] = power;   // channel 1
}

extern "C" void kernel_launch(void* const* d_in, const int* in_sizes, int n_in,
                              void* d_out, int out_size) {
    const float* xv    = (const float*)d_in[0]; // (1024,34,5)
    const float* dcoef = (const float*)d_in[1]; // (34,23)
    const float* dbase = (const float*)d_in[2]; // (34,)
    const float* ccoef = (const float*)d_in[3]; // (5,23)
    const float* cbase = (const float*)d_in[4]; // (5,)
    float* out = (float*)d_out;                 // (1024,2,256,256)

    fused_kernel<<<BB, 256>>>(xv, dcoef, dbase, ccoef, cbase, out);
}

// round 5
// speedup vs baseline: 1.0706x; 1.0387x over previous
#include <cuda_runtime.h>

// Problem constants (from reference)
#define KORD 8
#define NUMI 15
#define GBAS (NUMI + KORD)        // 23 basis functions
#define BB 1024
#define NN 34
#define HH 256
#define WW 256

#define BANDS 4                        // blocks per image (row bands)
#define BAND_ROWS (HH / BANDS)         // 64 rows per band
#define BAND_FLOATS (BAND_ROWS * WW)   // 16384 floats per band per channel
#define BAND_F4 (BAND_FLOATS / 4)      // 4096 float4 per band per channel
#define IMG_FLOATS (2 * HH * WW)       // 131072 floats per image

// Order-8 B-spline KAN edge via local de Boor: only the K+1=9 basis functions
// covering x are nonzero. Uniform knots (h = 4/15) make every denominator in
// the triangular recurrence equal to the constant j -> pure FFMA, 9 registers.
// Out-of-range x: all indicators in the reference are zero, so the spline sum
// vanishes and only base*silu survives.
__device__ __forceinline__ float spline_apply_one(float x, int id,
                                                  const float* __restrict__ coef,
                                                  const float* __restrict__ base) {
    float res = base[id] * (x / (1.0f + expf(-x)));   // base * silu(x)

    const float h    = 4.0f / 15.0f;
    const float invh = 15.0f / 4.0f;
    const float g0   = -2.0f - (float)KORD * h;       // grid[0]

    float u = (x - g0) * invh;                        // position in knot units
    float mf = floorf(u);
    int m = (int)mf;
    if (m < 0 || m > 30) return res;                  // outside knot range
    float t = u - mf;                                 // local coord in [0,1)

    // de Boor: N[r] = B_{m-8+r}(x) after the last iteration
    float N[KORD + 1];
    N[0] = 1.0f;
#pragma unroll
    for (int j = 1; j <= KORD; j++) {
        const float invj = 1.0f / (float)j;           // compile-time constant
        float saved = 0.0f;
#pragma unroll
        for (int r = 0; r < j; r++) {
            float temp = N[r] * invj;
            N[r] = saved + ((float)(r + 1) - t) * temp;
            saved = (t + (float)(j - 1 - r)) * temp;
        }
        N[j] = saved;
    }

    const float* crow = coef + id * GBAS;
#pragma unroll
    for (int r = 0; r <= KORD; r++) {
        int jdx = m - KORD + r;
        if (jdx >= 0 && jdx < GBAS)
            res += crow[jdx] * N[r];
    }
    return res;
}

// 4 blocks per image, each owning a 64-row band of BOTH channels (128 KB).
// Phase 1: zero the band (plain write-back float4 stores). Phase 2: block
// sync, then threads 0..33 evaluate points whose cy lies in this band and
// scatter into the block-owned region. No cross-block ordering needed.
__global__ void __launch_bounds__(256, 8)
fused_kernel(const float* __restrict__ xv,
             const float* __restrict__ dcoef,
             const float* __restrict__ dbase,
             const float* __restrict__ ccoef,
             const float* __restrict__ cbase,
             float* __restrict__ out) {
    const int blk = blockIdx.x;
    const int b = blk >> 2;            // image index
    const int band = blk & 3;          // row band within image

    float* img = out + (size_t)b * IMG_FLOATS;
    float* band0 = img + band * BAND_FLOATS;              // ch0 rows [64*band, ...)
    float* band1 = img + HH * WW + band * BAND_FLOATS;    // ch1 same rows
    const float4 z = make_float4(0.f, 0.f, 0.f, 0.f);

    float4* b04 = (float4*)band0;
    float4* b14 = (float4*)band1;
#pragma unroll 8
    for (int i = threadIdx.x; i < BAND_F4; i += 256) b04[i] = z;
#pragma unroll 8
    for (int i = threadIdx.x; i < BAND_F4; i += 256) b14[i] = z;

    __syncthreads();

    const int n = threadIdx.x;
    if (n >= NN) return;

    const float* vb = xv + (size_t)b * NN * 5;
    const float* v = vb + n * 5;
    float power = v[0];
    int cx = (int)rintf(v[1]);
    int cy = (int)rintf(v[2]);
    if ((cy >> 6) != band) return;     // not this block's band
    int dev = (int)v[3];
    int cat = (int)v[4];

    // Last-write-wins in index order: if any LATER point in this image hits
    // the same (cy,cx), this point's writes are dead — skip them.
    for (int m = n + 1; m < NN; m++) {
        int mx = (int)rintf(vb[m * 5 + 1]);
        int my = (int)rintf(vb[m * 5 + 2]);
        if (mx == cx && my == cy) return;
    }

    float p = spline_apply_one(power, dev, dcoef, dbase);
    p       = spline_apply_one(p,     cat, ccoef, cbase);

    int row_in_band = cy - band * BAND_ROWS;
    int off = row_in_band * WW + cx;
    band0[off] = p;        // channel 0
    band1[off] = power;    // channel 1
}

extern "C" void kernel_launch(void* const* d_in, const int* in_sizes, int n_in,
                              void* d_out, int out_size) {
    const float* xv    = (const float*)d_in[0]; // (1024,34,5)
    const float* dcoef = (const float*)d_in[1]; // (34,23)
    const float* dbase = (const float*)d_in[2]; // (34,)
    const float* ccoef = (const float*)d_in[3]; // (5,23)
    const float* cbase = (const float*)d_in[4]; // (5,)
    float* out = (float*)d_out;                 // (1024,2,256,256)

    fused_kernel<<<BB * BANDS, 256>>>(xv, dcoef, dbase, ccoef, cbase, out);
}

// round 6
// speedup vs baseline: 1.1193x; 1.0454x over previous
#include <cuda_runtime.h>

// Problem constants (from reference)
#define KORD 8
#define NUMI 15
#define GBAS (NUMI + KORD)        // 23 basis functions
#define BB 1024
#define NN 34
#define HH 256
#define WW 256

// Order-8 B-spline KAN edge via local de Boor: only the K+1=9 basis functions
// covering x are nonzero. Uniform knots (h = 4/15) make every denominator in
// the triangular recurrence a compile-time constant -> pure FFMA, 9 registers.
// Out-of-range x: all indicators in the reference are zero, so the spline sum
// vanishes and only base*silu survives.
__device__ __forceinline__ float spline_apply_one(float x, int id,
                                                  const float* __restrict__ coef,
                                                  const float* __restrict__ base) {
    float res = base[id] * (x / (1.0f + expf(-x)));   // base * silu(x)

    const float h    = 4.0f / 15.0f;
    const float invh = 15.0f / 4.0f;
    const float g0   = -2.0f - (float)KORD * h;       // grid[0]

    float u = (x - g0) * invh;                        // position in knot units
    float mf = floorf(u);
    int m = (int)mf;
    if (m < 0 || m > 30) return res;                  // outside knot range
    float t = u - mf;                                 // local coord in [0,1)

    // de Boor: N[r] = B_{m-8+r}(x) after the last iteration
    float N[KORD + 1];
    N[0] = 1.0f;
#pragma unroll
    for (int j = 1; j <= KORD; j++) {
        const float invj = 1.0f / (float)j;           // compile-time constant
        float saved = 0.0f;
#pragma unroll
        for (int r = 0; r < j; r++) {
            float temp = N[r] * invj;
            N[r] = saved + ((float)(r + 1) - t) * temp;
            saved = (t + (float)(j - 1 - r)) * temp;
        }
        N[j] = saved;
    }

    const float* crow = coef + id * GBAS;
#pragma unroll
    for (int r = 0; r <= KORD; r++) {
        int jdx = m - KORD + r;
        if (jdx >= 0 && jdx < GBAS)
            res += crow[jdx] * N[r];
    }
    return res;
}

// One thread per point (34816 total). Runs after the memset.
__global__ void __launch_bounds__(256)
scatter_kernel(const float* __restrict__ xv,
               const float* __restrict__ dcoef,
               const float* __restrict__ dbase,
               const float* __restrict__ ccoef,
               const float* __restrict__ cbase,
               float* __restrict__ out) {
    int idx = blockIdx.x * blockDim.x + threadIdx.x;
    if (idx >= BB * NN) return;
    int b = idx / NN;
    int n = idx % NN;

    const float* vb = xv + (size_t)b * NN * 5;
    const float* v = vb + n * 5;
    float power = v[0];
    int cx = (int)rintf(v[1]);
    int cy = (int)rintf(v[2]);
    int dev = (int)v[3];
    int cat = (int)v[4];

    // Last-write-wins in index order: if any LATER point in this image hits
    // the same (cy,cx), this point's writes are dead — skip them.
    for (int m = n + 1; m < NN; m++) {
        int mx = (int)rintf(vb[m * 5 + 1]);
        int my = (int)rintf(vb[m * 5 + 2]);
        if (mx == cx && my == cy) return;
    }

    float p = spline_apply_one(power, dev, dcoef, dbase);
    p       = spline_apply_one(p,     cat, ccoef, cbase);

    size_t base_off = (size_t)b * (2 * HH * WW);
    size_t pix = (size_t)cy * WW + cx;
    out[base_off + pix] = p;                 // channel 0
    out[base_off + HH * WW + pix] = power;   // channel 1
}

extern "C" void kernel_launch(void* const* d_in, const int* in_sizes, int n_in,
                              void* d_out, int out_size) {
    const float* xv    = (const float*)d_in[0]; // (1024,34,5)
    const float* dcoef = (const float*)d_in[1]; // (34,23)
    const float* dbase = (const float*)d_in[2]; // (34,)
    const float* ccoef = (const float*)d_in[3]; // (5,23)
    const float* cbase = (const float*)d_in[4]; // (5,)
    float* out = (float*)d_out;                 // (1024,2,256,256)

    // Phase 1: driver bulk zero-fill (graph memset node, no allocation).
    cudaMemsetAsync(out, 0, (size_t)out_size * sizeof(float), 0);

    // Phase 2: sparse scatter of 34816 spline-evaluated points.
    int npts = BB * NN;
    scatter_kernel<<<(npts + 255) / 256, 256>>>(xv, dcoef, dbase, ccoef, cbase, out);
}

// round 7
// speedup vs baseline: 1.1721x; 1.0472x over previous
#include <cuda_runtime.h>

// Problem constants (from reference)
#define KORD 8
#define NUMI 15
#define GBAS (NUMI + KORD)        // 23 basis functions
#define BB 1024
#define NN 34
#define HH 256
#define WW 256

// Order-8 B-spline KAN edge via local de Boor: only the K+1=9 basis functions
// covering x are nonzero. Uniform knots (h = 4/15) make every denominator in
// the triangular recurrence a compile-time constant -> pure FFMA, 9 registers.
// Out-of-range x: all indicators in the reference are zero, so the spline sum
// vanishes and only base*silu survives.
__device__ __forceinline__ float spline_apply_one(float x, int id,
                                                  const float* __restrict__ coef,
                                                  const float* __restrict__ base) {
    float res = base[id] * (x / (1.0f + expf(-x)));   // base * silu(x)

    const float invh = 15.0f / 4.0f;
    const float g0   = -2.0f - (float)KORD * (4.0f / 15.0f);  // grid[0]

    float u = (x - g0) * invh;                        // position in knot units
    float mf = floorf(u);
    int m = (int)mf;
    if (m < 0 || m > 30) return res;                  // outside knot range
    float t = u - mf;                                 // local coord in [0,1)

    // de Boor: N[r] = B_{m-8+r}(x) after the last iteration
    float N[KORD + 1];
    N[0] = 1.0f;
#pragma unroll
    for (int j = 1; j <= KORD; j++) {
        const float invj = 1.0f / (float)j;           // compile-time constant
        float saved = 0.0f;
#pragma unroll
        for (int r = 0; r < j; r++) {
            float temp = N[r] * invj;
            N[r] = saved + ((float)(r + 1) - t) * temp;
            saved = (t + (float)(j - 1 - r)) * temp;
        }
        N[j] = saved;
    }

    const float* crow = coef + id * GBAS;
#pragma unroll
    for (int r = 0; r <= KORD; r++) {
        int jdx = m - KORD + r;
        if (jdx >= 0 && jdx < GBAS)
            res += crow[jdx] * N[r];
    }
    return res;
}

// One block per image, 64 threads. Threads cooperatively stage the image's
// 170-float xv row in smem (coalesced), then threads 0..33 each handle one
// point: smem collision check (last-write-wins), two stacked spline evals,
// two scattered stores. Runs after the memset node.
__global__ void __launch_bounds__(64)
scatter_kernel(const float* __restrict__ xv,
               const float* __restrict__ dcoef,
               const float* __restrict__ dbase,
               const float* __restrict__ ccoef,
               const float* __restrict__ cbase,
               float* __restrict__ out) {
    __shared__ float s_xv[NN * 5];     // 680 B
    __shared__ int   s_cx[NN];
    __shared__ int   s_cy[NN];

    const int b = blockIdx.x;
    const int tid = threadIdx.x;
    const float* vb = xv + (size_t)b * NN * 5;

    // Coalesced stage of the whole image row (170 floats, 3 passes of 64)
#pragma unroll
    for (int i = tid; i < NN * 5; i += 64) s_xv[i] = vb[i];
    __syncthreads();

    const int n = tid;
    if (n >= NN) return;

    // Round coords once into smem for the collision scan
    int cx = (int)rintf(s_xv[n * 5 + 1]);
    int cy = (int)rintf(s_xv[n * 5 + 2]);
    s_cx[n] = cx;
    s_cy[n] = cy;
    __syncwarp(0xFFFFFFFF);            // lanes 0..31 of warp0
    // threads 32,33 are in warp1 — make their coords visible to warp0 and
    // vice versa with a cheap named sync over the 64-thread block:
    __syncthreads();

    float power = s_xv[n * 5 + 0];
    int dev = (int)s_xv[n * 5 + 3];
    int cat = (int)s_xv[n * 5 + 4];

    // Last-write-wins in index order: if any LATER point in this image hits
    // the same (cy,cx), this point's writes are dead — skip them.
    bool dead = false;
#pragma unroll 4
    for (int m = n + 1; m < NN; m++) {
        dead |= (s_cx[m] == cx) & (s_cy[m] == cy);
    }
    if (dead) return;

    float p = spline_apply_one(power, dev, dcoef, dbase);
    p       = spline_apply_one(p,     cat, ccoef, cbase);

    size_t base_off = (size_t)b * (2 * HH * WW);
    size_t pix = (size_t)cy * WW + cx;
    out[base_off + pix] = p;                 // channel 0
    out[base_off + HH * WW + pix] = power;   // channel 1
}

extern "C" void kernel_launch(void* const* d_in, const int* in_sizes, int n_in,
                              void* d_out, int out_size) {
    const float* xv    = (const float*)d_in[0]; // (1024,34,5)
    const float* dcoef = (const float*)d_in[1]; // (34,23)
    const float* dbase = (const float*)d_in[2]; // (34,)
    const float* ccoef = (const float*)d_in[3]; // (5,23)
    const float* cbase = (const float*)d_in[4]; // (5,)
    float* out = (float*)d_out;                 // (1024,2,256,256)

    // Phase 1: driver bulk zero-fill (graph memset node, ~7.2 TB/s).
    cudaMemsetAsync(out, 0, (size_t)out_size * sizeof(float), 0);

    // Phase 2: sparse scatter, one block per image.
    scatter_kernel<<<BB, 64>>>(xv, dcoef, dbase, ccoef, cbase, out);
}